// round 8
// baseline (speedup 1.0000x reference)
#include <cuda_runtime.h>

// DistMaps: out[b,g,r,c] = tanh(2*sqrt(min_p d2)) over 24 clicks per (b,g) group,
// d2 = ((r-pr)/5)^2 + ((c-pc)/5)^2, invalid clicks (max coords < 0) -> 1e6.
// x input (d_in[0]) is shape-only; output depends only on coords (d_in[1]).
//
// R8: R4-R7 showed duration (~7us) is invariant to instruction count, warp
// count and occupancy -> bound by fixed chip-level overhead (CTA dispatch,
// wave structure, T_ovh), not by any pipe. Keep R6's per-warp shape
// (4-row x 128-col window, warp-granular click cull) but repackage as
// 256 CTAs x 1024 threads (32 warps/CTA, ~1 CTA/SM, 1D grid) to cut CTA
// dispatch 4x and flatten the wave structure.
//
// d2 >= 41 => 2*sqrt(d2) >= 12.8 => tanh rounds to exactly 1.0f, so clamping
// the min at 41 and writing 1.0f for unreached pixels is exact.

namespace {

constexpr int   H         = 512;
constexpr int   W         = 512;
constexpr int   P         = 24;      // clicks per group
constexpr float INV_SCALE = 0.2f;    // 1 / (NORM_RADIUS * SPATIAL_SCALE)
constexpr float CULL_D2   = 41.0f;

__device__ __forceinline__ float tanh_2sqrt_fast(float q) {
    float s, t;
    asm("sqrt.approx.f32 %0, %1;" : "=f"(s) : "f"(q));
    s = 2.0f * s;
    asm("tanh.approx.f32 %0, %1;" : "=f"(t) : "f"(s));
    return t;
}

__global__ __launch_bounds__(1024, 1) void distmaps_kernel(
    const float* __restrict__ coords,   // [B, 48, 3] (row, col, _)
    float*       __restrict__ out)      // [B, 2, H, W]
{
    const int tid  = threadIdx.x;
    const int wid  = tid >> 5;
    const int lane = tid & 31;

    // Global warp id -> (group, window). 512 windows of 4x128 per group.
    const int g    = blockIdx.x * 32 + wid;      // 0 .. 8191
    const int bg   = g >> 9;                     // 0..15
    const int wloc = g & 511;
    const int r0   = (wloc >> 2) << 2;           // window row base (4 rows)
    const int c0   = (wloc & 3)  << 7;           // window col base (128 cols)

    // Lane p holds click p; test click against this warp's 4x128 window.
    float prs = 0.0f, pcs = 0.0f;
    bool  near = false;
    if (lane < P) {
        const float* cp = coords + (size_t)(bg * P + lane) * 3;
        const float pr = __ldg(cp);
        const float pc = __ldg(cp + 1);
        const bool valid = fmaxf(pr, pc) >= 0.0f;    // invalid iff both < 0
        const float rr = fminf(fmaxf(pr, (float)r0), (float)(r0 + 3));
        const float cc = fminf(fmaxf(pc, (float)c0), (float)(c0 + 127));
        const float dr = (rr - pr) * INV_SCALE;
        const float dc = (cc - pc) * INV_SCALE;
        near = valid && (fmaf(dr, dr, dc * dc) < CULL_D2);
        prs = pr * INV_SCALE;
        pcs = pc * INV_SCALE;
    }
    unsigned mask = __ballot_sync(0xffffffffu, near);

    const int colq = c0 + lane * 4;              // this thread's 4 columns
    float* obase = out + ((size_t)bg * H + r0) * W + colq;

    if (mask == 0u) {
        // No click reaches this window: every pixel is exactly 1.0f.
        const float4 ones = make_float4(1.0f, 1.0f, 1.0f, 1.0f);
#pragma unroll
        for (int i = 0; i < 4; ++i)
            *reinterpret_cast<float4*>(obase + (size_t)i * W) = ones;
        return;
    }

    const float a0  = (float)(colq + 0) * INV_SCALE;
    const float a1  = (float)(colq + 1) * INV_SCALE;
    const float a2  = (float)(colq + 2) * INV_SCALE;
    const float a3  = (float)(colq + 3) * INV_SCALE;
    const float rs0 = (float)(r0 + 0) * INV_SCALE;
    const float rs1 = (float)(r0 + 1) * INV_SCALE;
    const float rs2 = (float)(r0 + 2) * INV_SCALE;
    const float rs3 = (float)(r0 + 3) * INV_SCALE;

    float q[4][4];
#pragma unroll
    for (int i = 0; i < 4; ++i)
#pragma unroll
        for (int j = 0; j < 4; ++j) q[i][j] = CULL_D2;

    // Iterate surviving clicks (warp-uniform mask -> no divergence).
    while (mask) {
        const int p = __ffs(mask) - 1;
        mask &= mask - 1;
        const float pr = __shfl_sync(0xffffffffu, prs, p);
        const float pc = __shfl_sync(0xffffffffu, pcs, p);

        const float dc0 = a0 - pc, dc1 = a1 - pc, dc2 = a2 - pc, dc3 = a3 - pc;
        float dr, e;
        dr = rs0 - pr; e = dr * dr;
        q[0][0] = fminf(q[0][0], fmaf(dc0, dc0, e));
        q[0][1] = fminf(q[0][1], fmaf(dc1, dc1, e));
        q[0][2] = fminf(q[0][2], fmaf(dc2, dc2, e));
        q[0][3] = fminf(q[0][3], fmaf(dc3, dc3, e));
        dr = rs1 - pr; e = dr * dr;
        q[1][0] = fminf(q[1][0], fmaf(dc0, dc0, e));
        q[1][1] = fminf(q[1][1], fmaf(dc1, dc1, e));
        q[1][2] = fminf(q[1][2], fmaf(dc2, dc2, e));
        q[1][3] = fminf(q[1][3], fmaf(dc3, dc3, e));
        dr = rs2 - pr; e = dr * dr;
        q[2][0] = fminf(q[2][0], fmaf(dc0, dc0, e));
        q[2][1] = fminf(q[2][1], fmaf(dc1, dc1, e));
        q[2][2] = fminf(q[2][2], fmaf(dc2, dc2, e));
        q[2][3] = fminf(q[2][3], fmaf(dc3, dc3, e));
        dr = rs3 - pr; e = dr * dr;
        q[3][0] = fminf(q[3][0], fmaf(dc0, dc0, e));
        q[3][1] = fminf(q[3][1], fmaf(dc1, dc1, e));
        q[3][2] = fminf(q[3][2], fmaf(dc2, dc2, e));
        q[3][3] = fminf(q[3][3], fmaf(dc3, dc3, e));
    }

    // Per-row epilogue with warp vote to skip MUFU on fully saturated rows.
#pragma unroll
    for (int i = 0; i < 4; ++i) {
        const float rmin = fminf(fminf(q[i][0], q[i][1]), fminf(q[i][2], q[i][3]));
        float4 v;
        if (__all_sync(0xffffffffu, rmin >= CULL_D2)) {
            v = make_float4(1.0f, 1.0f, 1.0f, 1.0f);
        } else {
            v.x = tanh_2sqrt_fast(q[i][0]);
            v.y = tanh_2sqrt_fast(q[i][1]);
            v.z = tanh_2sqrt_fast(q[i][2]);
            v.w = tanh_2sqrt_fast(q[i][3]);
        }
        *reinterpret_cast<float4*>(obase + (size_t)i * W) = v;
    }
}

}  // namespace

extern "C" void kernel_launch(void* const* d_in, const int* in_sizes, int n_in,
                              void* d_out, int out_size) {
    // d_in[0]: x [B,3,512,512] f32 (unused), d_in[1]: coords [B,48,3] f32
    const float* coords = (const float*)d_in[1];
    float* out = (float*)d_out;

    const int B = in_sizes[1] / (48 * 3);     // 8
    const int nwarps = B * 2 * 512;           // 8192 warp windows
    distmaps_kernel<<<nwarps / 32, 1024>>>(coords, out);
}

// round 9
// speedup vs baseline: 1.2007x; 1.2007x over previous
#include <cuda_runtime.h>

// DistMaps: out[b,g,r,c] = tanh(2*sqrt(min_p d2)) over 24 clicks per (b,g) group,
// d2 = ((r-pr)/5)^2 + ((c-pc)/5)^2, invalid clicks (max coords < 0) -> 1e6.
// x input (d_in[0]) is shape-only; output depends only on coords (d_in[1]).
//
// R9: R6 shape (4x128 window per warp, 256-thr CTAs — best measured kernel dur)
// with serialization points removed: ONE warp vote per window (was 4 per-row
// votes), fully branchless MUFU epilogue for active windows. R8 falsified the
// CTA-dispatch theory; R1-R8 showed time is insensitive to instruction count
// but carries heavy per-warp control overhead (votes/branches/dependency
// chains), so this round cuts critical-path sync ops, not just instructions.
//
// d2 >= 41 => 2*sqrt(d2) >= 12.8 => tanh rounds to exactly 1.0f, so clamping
// the min at 41 and writing 1.0f for unreached pixels is exact.

namespace {

constexpr int   H         = 512;
constexpr int   W         = 512;
constexpr int   P         = 24;      // clicks per group
constexpr float INV_SCALE = 0.2f;    // 1 / (NORM_RADIUS * SPATIAL_SCALE)
constexpr float CULL_D2   = 41.0f;

__device__ __forceinline__ float tanh_2sqrt_fast(float q) {
    float s, t;
    asm("sqrt.approx.f32 %0, %1;" : "=f"(s) : "f"(q));
    s = 2.0f * s;
    asm("tanh.approx.f32 %0, %1;" : "=f"(t) : "f"(s));
    return t;
}

__global__ __launch_bounds__(256) void distmaps_kernel(
    const float* __restrict__ coords,   // [B, 48, 3] (row, col, _)
    float*       __restrict__ out)      // [B, 2, H, W]
{
    const int tid  = threadIdx.x;
    const int wid  = tid >> 5;
    const int lane = tid & 31;
    const int bg   = blockIdx.y;                 // 0..2B-1

    const int wloc = blockIdx.x * 8 + wid;       // 0..511 window slot in group
    const int r0   = (wloc >> 2) << 2;           // window row base (4 rows)
    const int c0   = (wloc & 3)  << 7;           // window col base (128 cols)

    // Lane p holds click p; test click against this warp's 4x128 window.
    float prs = 0.0f, pcs = 0.0f;
    bool  near = false;
    if (lane < P) {
        const float* cp = coords + (size_t)(bg * P + lane) * 3;
        const float pr = __ldg(cp);
        const float pc = __ldg(cp + 1);
        const bool valid = fmaxf(pr, pc) >= 0.0f;    // invalid iff both < 0
        const float rr = fminf(fmaxf(pr, (float)r0), (float)(r0 + 3));
        const float cc = fminf(fmaxf(pc, (float)c0), (float)(c0 + 127));
        const float dr = (rr - pr) * INV_SCALE;
        const float dc = (cc - pc) * INV_SCALE;
        near = valid && (fmaf(dr, dr, dc * dc) < CULL_D2);
        prs = pr * INV_SCALE;
        pcs = pc * INV_SCALE;
    }
    unsigned mask = __ballot_sync(0xffffffffu, near);

    const int colq = c0 + lane * 4;              // this thread's 4 columns
    float* obase = out + ((size_t)bg * H + r0) * W + colq;

    if (mask == 0u) {
        // No click reaches this window: every pixel is exactly 1.0f.
        const float4 ones = make_float4(1.0f, 1.0f, 1.0f, 1.0f);
#pragma unroll
        for (int i = 0; i < 4; ++i)
            *reinterpret_cast<float4*>(obase + (size_t)i * W) = ones;
        return;
    }

    const float a0  = (float)(colq + 0) * INV_SCALE;
    const float a1  = (float)(colq + 1) * INV_SCALE;
    const float a2  = (float)(colq + 2) * INV_SCALE;
    const float a3  = (float)(colq + 3) * INV_SCALE;
    const float rs0 = (float)(r0 + 0) * INV_SCALE;
    const float rs1 = (float)(r0 + 1) * INV_SCALE;
    const float rs2 = (float)(r0 + 2) * INV_SCALE;
    const float rs3 = (float)(r0 + 3) * INV_SCALE;

    float q[4][4];
#pragma unroll
    for (int i = 0; i < 4; ++i)
#pragma unroll
        for (int j = 0; j < 4; ++j) q[i][j] = CULL_D2;

    // Iterate surviving clicks (warp-uniform mask -> no divergence).
    while (mask) {
        const int p = __ffs(mask) - 1;
        mask &= mask - 1;
        const float pr = __shfl_sync(0xffffffffu, prs, p);
        const float pc = __shfl_sync(0xffffffffu, pcs, p);

        const float dc0 = a0 - pc, dc1 = a1 - pc, dc2 = a2 - pc, dc3 = a3 - pc;
        float dr, e;
        dr = rs0 - pr; e = dr * dr;
        q[0][0] = fminf(q[0][0], fmaf(dc0, dc0, e));
        q[0][1] = fminf(q[0][1], fmaf(dc1, dc1, e));
        q[0][2] = fminf(q[0][2], fmaf(dc2, dc2, e));
        q[0][3] = fminf(q[0][3], fmaf(dc3, dc3, e));
        dr = rs1 - pr; e = dr * dr;
        q[1][0] = fminf(q[1][0], fmaf(dc0, dc0, e));
        q[1][1] = fminf(q[1][1], fmaf(dc1, dc1, e));
        q[1][2] = fminf(q[1][2], fmaf(dc2, dc2, e));
        q[1][3] = fminf(q[1][3], fmaf(dc3, dc3, e));
        dr = rs2 - pr; e = dr * dr;
        q[2][0] = fminf(q[2][0], fmaf(dc0, dc0, e));
        q[2][1] = fminf(q[2][1], fmaf(dc1, dc1, e));
        q[2][2] = fminf(q[2][2], fmaf(dc2, dc2, e));
        q[2][3] = fminf(q[2][3], fmaf(dc3, dc3, e));
        dr = rs3 - pr; e = dr * dr;
        q[3][0] = fminf(q[3][0], fmaf(dc0, dc0, e));
        q[3][1] = fminf(q[3][1], fmaf(dc1, dc1, e));
        q[3][2] = fminf(q[3][2], fmaf(dc2, dc2, e));
        q[3][3] = fminf(q[3][3], fmaf(dc3, dc3, e));
    }

    // Single vote for the whole window; active path is fully branchless.
    float wmin = CULL_D2;
#pragma unroll
    for (int i = 0; i < 4; ++i)
#pragma unroll
        for (int j = 0; j < 4; ++j) wmin = fminf(wmin, q[i][j]);

    if (__any_sync(0xffffffffu, wmin < CULL_D2)) {
#pragma unroll
        for (int i = 0; i < 4; ++i) {
            float4 v;
            v.x = tanh_2sqrt_fast(q[i][0]);
            v.y = tanh_2sqrt_fast(q[i][1]);
            v.z = tanh_2sqrt_fast(q[i][2]);
            v.w = tanh_2sqrt_fast(q[i][3]);
            *reinterpret_cast<float4*>(obase + (size_t)i * W) = v;
        }
    } else {
        const float4 ones = make_float4(1.0f, 1.0f, 1.0f, 1.0f);
#pragma unroll
        for (int i = 0; i < 4; ++i)
            *reinterpret_cast<float4*>(obase + (size_t)i * W) = ones;
    }
}

}  // namespace

extern "C" void kernel_launch(void* const* d_in, const int* in_sizes, int n_in,
                              void* d_out, int out_size) {
    // d_in[0]: x [B,3,512,512] f32 (unused), d_in[1]: coords [B,48,3] f32
    const float* coords = (const float*)d_in[1];
    float* out = (float*)d_out;

    const int B = in_sizes[1] / (48 * 3);   // 8
    dim3 grid(64, B * 2);                   // 64 blocks x 16 groups, 8 warps each
    distmaps_kernel<<<grid, 256>>>(coords, out);
}

// round 10
// speedup vs baseline: 1.2316x; 1.0257x over previous
#include <cuda_runtime.h>

// DistMaps: out[b,g,r,c] = tanh(2*sqrt(min_p d2)) over 24 clicks per (b,g) group,
// d2 = ((r-pr)/5)^2 + ((c-pc)/5)^2, invalid clicks (max coords < 0) -> 1e6.
// x input (d_in[0]) is shape-only; output depends only on coords (d_in[1]).
//
// R10: R6/R9 shape (4x128 window per warp, 256-thr CTAs, warp-granular click
// cull, single window vote, 3-instr MUFU epilogue) with an instruction diet:
// R9's profile showed ~458 issued instr/warp at 49% issue efficiency at
// ~1.8GHz -> purely issue-count bound. This round: bit-packed output index
// (bg/r0/c0/lane occupy disjoint bits -> OR instead of IMAD chains),
// incremental I2F-free coordinate setup, minimal branch regions.
//
// d2 >= 41 => 2*sqrt(d2) >= 12.8 => tanh rounds to exactly 1.0f, so clamping
// the min at 41 and writing 1.0f for unreached pixels is exact.

namespace {

constexpr int   W         = 512;
constexpr int   P         = 24;      // clicks per group
constexpr float INV_SCALE = 0.2f;    // 1 / (NORM_RADIUS * SPATIAL_SCALE)
constexpr float CULL_D2   = 41.0f;

__device__ __forceinline__ float tanh_2sqrt_fast(float q) {
    float s, t;
    asm("sqrt.approx.f32 %0, %1;" : "=f"(s) : "f"(q));
    s = 2.0f * s;
    asm("tanh.approx.f32 %0, %1;" : "=f"(t) : "f"(s));
    return t;
}

__global__ __launch_bounds__(256, 6) void distmaps_kernel(
    const float* __restrict__ coords,   // [B, 48, 3] (row, col, _)
    float*       __restrict__ out)      // [B, 2, H, W]
{
    const int tid  = threadIdx.x;
    const int lane = tid & 31;
    const int bg   = blockIdx.y;                   // 0..2B-1

    const int wloc = (blockIdx.x << 3) + (tid >> 5);  // 0..511 window in group
    const int r0   = (wloc >> 2) << 2;             // window row base (4 rows)
    const int c0   = (wloc & 3) << 7;              // window col base (128 cols)

    // Lane p holds click p; test click against this warp's 4x128 window.
    float prs = 0.0f, pcs = 0.0f;
    bool  near = false;
    if (lane < P) {
        const float* cp = coords + (bg * P + lane) * 3;
        const float pr = __ldg(cp);
        const float pc = __ldg(cp + 1);
        const bool valid = fmaxf(pr, pc) >= 0.0f;      // invalid iff both < 0
        const float rr = fminf(fmaxf(pr, (float)r0), (float)(r0 + 3));
        const float cc = fminf(fmaxf(pc, (float)c0), (float)(c0 + 127));
        const float dr = (rr - pr) * INV_SCALE;
        const float dc = (cc - pc) * INV_SCALE;
        near = valid && (fmaf(dr, dr, dc * dc) < CULL_D2);
        prs = pr * INV_SCALE;
        pcs = pc * INV_SCALE;
    }
    unsigned mask = __ballot_sync(0xffffffffu, near);

    // Output index: bg<<18 | r0<<9 | c0 | lane<<2 (disjoint bit fields).
    const unsigned idx = ((unsigned)bg << 18) | ((unsigned)r0 << 9) |
                         (unsigned)(c0 | (lane << 2));
    float* obase = out + idx;

    if (mask == 0u) {
        // No click reaches this window: every pixel is exactly 1.0f.
        const float4 ones = make_float4(1.0f, 1.0f, 1.0f, 1.0f);
#pragma unroll
        for (int i = 0; i < 4; ++i)
            *reinterpret_cast<float4*>(obase + i * W) = ones;
        return;
    }

    // Incremental coordinate setup (1 I2F + 1 FMUL + 3 FADD per axis).
    const float a0  = (float)(c0 | (lane << 2)) * INV_SCALE;
    const float a1  = a0 + INV_SCALE;
    const float a2  = a1 + INV_SCALE;
    const float a3  = a2 + INV_SCALE;
    const float rs0 = (float)r0 * INV_SCALE;
    const float rs1 = rs0 + INV_SCALE;
    const float rs2 = rs1 + INV_SCALE;
    const float rs3 = rs2 + INV_SCALE;

    float q[4][4];
#pragma unroll
    for (int i = 0; i < 4; ++i)
#pragma unroll
        for (int j = 0; j < 4; ++j) q[i][j] = CULL_D2;

    // Iterate surviving clicks (warp-uniform mask -> no divergence).
    while (mask) {
        const int p = __ffs(mask) - 1;
        mask &= mask - 1;
        const float pr = __shfl_sync(0xffffffffu, prs, p);
        const float pc = __shfl_sync(0xffffffffu, pcs, p);

        const float dc0 = a0 - pc, dc1 = a1 - pc, dc2 = a2 - pc, dc3 = a3 - pc;
        float dr, e;
        dr = rs0 - pr; e = dr * dr;
        q[0][0] = fminf(q[0][0], fmaf(dc0, dc0, e));
        q[0][1] = fminf(q[0][1], fmaf(dc1, dc1, e));
        q[0][2] = fminf(q[0][2], fmaf(dc2, dc2, e));
        q[0][3] = fminf(q[0][3], fmaf(dc3, dc3, e));
        dr = rs1 - pr; e = dr * dr;
        q[1][0] = fminf(q[1][0], fmaf(dc0, dc0, e));
        q[1][1] = fminf(q[1][1], fmaf(dc1, dc1, e));
        q[1][2] = fminf(q[1][2], fmaf(dc2, dc2, e));
        q[1][3] = fminf(q[1][3], fmaf(dc3, dc3, e));
        dr = rs2 - pr; e = dr * dr;
        q[2][0] = fminf(q[2][0], fmaf(dc0, dc0, e));
        q[2][1] = fminf(q[2][1], fmaf(dc1, dc1, e));
        q[2][2] = fminf(q[2][2], fmaf(dc2, dc2, e));
        q[2][3] = fminf(q[2][3], fmaf(dc3, dc3, e));
        dr = rs3 - pr; e = dr * dr;
        q[3][0] = fminf(q[3][0], fmaf(dc0, dc0, e));
        q[3][1] = fminf(q[3][1], fmaf(dc1, dc1, e));
        q[3][2] = fminf(q[3][2], fmaf(dc2, dc2, e));
        q[3][3] = fminf(q[3][3], fmaf(dc3, dc3, e));
    }

    // Single vote for the whole window; active path is fully branchless.
    float wmin = CULL_D2;
#pragma unroll
    for (int i = 0; i < 4; ++i)
#pragma unroll
        for (int j = 0; j < 4; ++j) wmin = fminf(wmin, q[i][j]);

    if (__any_sync(0xffffffffu, wmin < CULL_D2)) {
#pragma unroll
        for (int i = 0; i < 4; ++i) {
            float4 v;
            v.x = tanh_2sqrt_fast(q[i][0]);
            v.y = tanh_2sqrt_fast(q[i][1]);
            v.z = tanh_2sqrt_fast(q[i][2]);
            v.w = tanh_2sqrt_fast(q[i][3]);
            *reinterpret_cast<float4*>(obase + i * W) = v;
        }
    } else {
        const float4 ones = make_float4(1.0f, 1.0f, 1.0f, 1.0f);
#pragma unroll
        for (int i = 0; i < 4; ++i)
            *reinterpret_cast<float4*>(obase + i * W) = ones;
    }
}

}  // namespace

extern "C" void kernel_launch(void* const* d_in, const int* in_sizes, int n_in,
                              void* d_out, int out_size) {
    // d_in[0]: x [B,3,512,512] f32 (unused), d_in[1]: coords [B,48,3] f32
    const float* coords = (const float*)d_in[1];
    float* out = (float*)d_out;

    const int B = in_sizes[1] / (48 * 3);   // 8
    dim3 grid(64, B * 2);                   // 64 blocks x 16 groups, 8 warps each
    distmaps_kernel<<<grid, 256>>>(coords, out);
}